// round 16
// baseline (speedup 1.0000x reference)
#include <cuda_runtime.h>
#include <cuda_bf16.h>
#include <cstdint>

// QLoRA rank-2 fused kernel, warp-per-row (no CTA barriers in mainloop):
//   h[r]   = a_scale[r] * sum_d x[row,d] * a_q[r,d]
//   out[d] = 0.5 * b_scale[d] * (h0 * b_q[d,0] + h1 * b_q[d,1])
//
// int8 weights arrive widened to int32 (harness dtype set). Dequantized
// weights live in 48KB smem per CTA:
//   sA0/sA1: a_q rows as bf16 (int8 values are EXACT in bf16)  -> 8KB each
//   sB0/sB1: b_scale[d]*b_q[d,r] as fp32 SoA float4            -> 16KB each
// Each warp processes whole rows (128 floats/lane): phase-1 reduce is
// warp-shuffle only, phase-2 follows in-warp. 8 float4 LDGs batched per
// unroll step keep MLP high; rows pipeline back-to-back with no barriers.

#define INNER_D  4096
#define NTH      256
#define NWARP    (NTH / 32)
#define GRID     1024

__device__ __forceinline__ float2 bf2_to_f2(unsigned u) {
    __nv_bfloat162 p = *reinterpret_cast<__nv_bfloat162*>(&u);
    return __bfloat1622float2(p);
}

__global__ __launch_bounds__(NTH, 3)
void qlora_warprow_kernel(const float* __restrict__ x,
                          const int*   __restrict__ aq,      // [2, 4096] int32
                          const float* __restrict__ ascale,  // [2]
                          const int*   __restrict__ bq,      // [4096, 2] int32
                          const float* __restrict__ bscale,  // [4096]
                          float* __restrict__ out,
                          int nrows) {
    __shared__ uint2  sA0[INNER_D / 4];   // 4 bf16 per entry (d..d+3), row 0
    __shared__ uint2  sA1[INNER_D / 4];   // row 1
    __shared__ float4 sB0[INNER_D / 4];   // b_scale[d]*b_q[d,0]
    __shared__ float4 sB1[INNER_D / 4];   // b_scale[d]*b_q[d,1]

    const int t = threadIdx.x;

    // ---- Dequantize weights into smem (once per CTA) ----
    for (int idx = t; idx < INNER_D / 4; idx += NTH) {
        const int d = idx * 4;
        const int4 a0 = *reinterpret_cast<const int4*>(aq + d);
        const int4 a1 = *reinterpret_cast<const int4*>(aq + INNER_D + d);
        __nv_bfloat162 lo, hi;
        uint2 u;
        lo.x = __float2bfloat16_rn((float)a0.x);
        lo.y = __float2bfloat16_rn((float)a0.y);
        hi.x = __float2bfloat16_rn((float)a0.z);
        hi.y = __float2bfloat16_rn((float)a0.w);
        u.x = *reinterpret_cast<unsigned*>(&lo);
        u.y = *reinterpret_cast<unsigned*>(&hi);
        sA0[idx] = u;
        lo.x = __float2bfloat16_rn((float)a1.x);
        lo.y = __float2bfloat16_rn((float)a1.y);
        hi.x = __float2bfloat16_rn((float)a1.z);
        hi.y = __float2bfloat16_rn((float)a1.w);
        u.x = *reinterpret_cast<unsigned*>(&lo);
        u.y = *reinterpret_cast<unsigned*>(&hi);
        sA1[idx] = u;

        // b_q[d][r]: int32 pairs, row-major [4096,2]
        const int4 b01 = *reinterpret_cast<const int4*>(bq + 2 * d);      // (d,0)(d,1)(d+1,0)(d+1,1)
        const int4 b23 = *reinterpret_cast<const int4*>(bq + 2 * d + 4);  // (d+2,0)..(d+3,1)
        const float4 bs = *reinterpret_cast<const float4*>(bscale + d);
        sB0[idx] = make_float4(bs.x * (float)b01.x, bs.y * (float)b01.z,
                               bs.z * (float)b23.x, bs.w * (float)b23.z);
        sB1[idx] = make_float4(bs.x * (float)b01.y, bs.y * (float)b01.w,
                               bs.z * (float)b23.y, bs.w * (float)b23.w);
    }
    __syncthreads();   // the only CTA barrier

    const float as0 = ascale[0] * 0.5f;   // fold lora_alpha/rank = 0.5
    const float as1 = ascale[1] * 0.5f;

    const int lane = t & 31;
    const int wid  = t >> 5;
    const int gw      = blockIdx.x * NWARP + wid;
    const int wstride = gridDim.x * NWARP;

    for (int row = gw; row < nrows; row += wstride) {
        const float* xr = x + (size_t)row * INNER_D;

        // ---- Phase 1: rank-2 dot product, 128 floats per lane ----
        float s0 = 0.f, s1 = 0.f;
        #pragma unroll
        for (int o = 0; o < 4; o++) {
            float4 xv[8];
            #pragma unroll
            for (int j = 0; j < 8; j++)
                xv[j] = *reinterpret_cast<const float4*>(
                            xr + o * 1024 + j * 128 + lane * 4);
            #pragma unroll
            for (int j = 0; j < 8; j++) {
                const int q = (o * 1024 + j * 128) / 4 + lane;   // uint2 idx
                const uint2 ua = sA0[q];
                const uint2 ub = sA1[q];
                const float2 a0l = bf2_to_f2(ua.x), a0h = bf2_to_f2(ua.y);
                const float2 a1l = bf2_to_f2(ub.x), a1h = bf2_to_f2(ub.y);
                s0 = fmaf(xv[j].x, a0l.x, s0);
                s0 = fmaf(xv[j].y, a0l.y, s0);
                s0 = fmaf(xv[j].z, a0h.x, s0);
                s0 = fmaf(xv[j].w, a0h.y, s0);
                s1 = fmaf(xv[j].x, a1l.x, s1);
                s1 = fmaf(xv[j].y, a1l.y, s1);
                s1 = fmaf(xv[j].z, a1h.x, s1);
                s1 = fmaf(xv[j].w, a1h.y, s1);
            }
        }

        // ---- Warp-only reduce (all lanes end with the full sum) ----
        #pragma unroll
        for (int o = 16; o > 0; o >>= 1) {
            s0 += __shfl_xor_sync(0xffffffffu, s0, o);
            s1 += __shfl_xor_sync(0xffffffffu, s1, o);
        }
        const float h0 = s0 * as0;
        const float h1 = s1 * as1;

        // ---- Phase 2: rank-2 expansion, weights from smem ----
        float* outr = out + (size_t)row * INNER_D;
        #pragma unroll 8
        for (int i = 0; i < 32; i++) {
            const int q = i * 32 + lane;
            const float4 b0 = sB0[q];
            const float4 b1 = sB1[q];
            float4 o4;
            o4.x = fmaf(h0, b0.x, h1 * b1.x);
            o4.y = fmaf(h0, b0.y, h1 * b1.y);
            o4.z = fmaf(h0, b0.z, h1 * b1.z);
            o4.w = fmaf(h0, b0.w, h1 * b1.w);
            *reinterpret_cast<float4*>(outr + i * 128 + lane * 4) = o4;
        }
    }
}

extern "C" void kernel_launch(void* const* d_in, const int* in_sizes, int n_in,
                              void* d_out, int out_size) {
    // Bind inputs by element count (robust to metadata ordering):
    //   67108864 -> x_in, 2 -> a_scale, 4096 -> b_scale,
    //   8192 (x2) -> a_q (first), b_q (second).
    const float* x      = nullptr;
    const int*   aq     = nullptr;
    const float* ascale = nullptr;
    const int*   bq     = nullptr;
    const float* bscale = nullptr;

    for (int i = 0; i < n_in; i++) {
        const int sz = in_sizes[i];
        if (sz == 2) {
            ascale = (const float*)d_in[i];
        } else if (sz == 4096) {
            bscale = (const float*)d_in[i];
        } else if (sz == 8192) {
            if (aq == nullptr) aq = (const int*)d_in[i];
            else               bq = (const int*)d_in[i];
        } else {
            x = (const float*)d_in[i];
        }
    }

    float* out = (float*)d_out;
    const int nrows = out_size / INNER_D;   // 16384
    qlora_warprow_kernel<<<GRID, NTH>>>(x, aq, ascale, bq, bscale, out, nrows);
}

// round 17
// speedup vs baseline: 2.2671x; 2.2671x over previous
#include <cuda_runtime.h>
#include <cstdint>

// QLoRA rank-2 fused kernel, R17:
//   h[r]   = a_scale[r] * sum_d x[row,d] * a_q[r,d]
//   out[d] = 0.5 * b_scale[d] * (h0 * b_q[d,0] + h1 * b_q[d,1])
//
// int8 weights arrive widened to int32 (harness dtype set {f32,i32,bf16}).
//
// Layout lessons from R10/R16: CTA streams CONSECUTIVE rows (DRAM locality;
// warp-per-row doubled DRAM traffic). This version:
//  - all dequantized weights in 64KB smem (fp32 SoA float4) -> ~60 regs,
//    3 CTAs/SM (smem-limited), 24 warps/SM
//  - 2 rows per iteration: 8 batched LDG.128 per thread (MLP=8), B weights
//    read once from smem per 2 rows, barrier frequency halved
//  - exactly ONE __syncthreads per 2 rows: warp-shuffle reduce -> smem
//    partials (double-buffered) -> redundant per-thread final sum
//  - streaming stores (__stcs) for out

#define INNER_D   4096
#define NTH       256
#define NWARP     (NTH / 32)
#define R_PER_CTA 16
#define NQ        (INNER_D / 4)   // 1024 float4 per weight array

__global__ __launch_bounds__(NTH, 3)
void qlora_r17_kernel(const float* __restrict__ x,
                      const int*   __restrict__ aq,      // [2, 4096] int32
                      const float* __restrict__ ascale,  // [2]
                      const int*   __restrict__ bq,      // [4096, 2] int32
                      const float* __restrict__ bscale,  // [4096]
                      float* __restrict__ out,
                      int nrows) {
    __shared__ float4 sA0[NQ];            // a_q row 0 (fp32, exact)
    __shared__ float4 sA1[NQ];            // a_q row 1
    __shared__ float4 sB0[NQ];            // b_scale[d]*b_q[d,0]
    __shared__ float4 sB1[NQ];            // b_scale[d]*b_q[d,1]
    __shared__ float4 part[2][NWARP];     // double-buffered warp partials

    const int t = threadIdx.x;

    // ---- Dequantize weights into smem (once per CTA) ----
    #pragma unroll
    for (int idx = t; idx < NQ; idx += NTH) {
        const int d = idx * 4;
        const int4 a0 = *reinterpret_cast<const int4*>(aq + d);
        const int4 a1 = *reinterpret_cast<const int4*>(aq + INNER_D + d);
        sA0[idx] = make_float4((float)a0.x, (float)a0.y, (float)a0.z, (float)a0.w);
        sA1[idx] = make_float4((float)a1.x, (float)a1.y, (float)a1.z, (float)a1.w);
        // b_q row-major [4096,2]: (d,0)(d,1)(d+1,0)(d+1,1)...
        const int4 b01 = *reinterpret_cast<const int4*>(bq + 2 * d);
        const int4 b23 = *reinterpret_cast<const int4*>(bq + 2 * d + 4);
        const float4 bs = *reinterpret_cast<const float4*>(bscale + d);
        sB0[idx] = make_float4(bs.x * (float)b01.x, bs.y * (float)b01.z,
                               bs.z * (float)b23.x, bs.w * (float)b23.z);
        sB1[idx] = make_float4(bs.x * (float)b01.y, bs.y * (float)b01.w,
                               bs.z * (float)b23.y, bs.w * (float)b23.w);
    }
    __syncthreads();

    const float as0 = ascale[0] * 0.5f;   // fold lora_alpha/rank = 0.5
    const float as1 = ascale[1] * 0.5f;

    const int wid  = t >> 5;
    const int lane = t & 31;
    const int row0 = blockIdx.x * R_PER_CTA;

    #pragma unroll 1
    for (int it = 0; it < R_PER_CTA / 2; it++) {
        const int rowA = row0 + it * 2;
        if (rowA >= nrows) break;
        const float* xrA = x + (size_t)rowA * INNER_D;
        const float* xrB = xrA + INNER_D;          // rowA+1 (nrows is even)
        const int buf = it & 1;

        // ---- Phase 1: load 2 rows (8 batched LDG.128), rank-2 dots ----
        float4 xa[4], xb[4];
        #pragma unroll
        for (int i = 0; i < 4; i++) {
            const int q = i * NTH + t;             // float4 index, coalesced
            xa[i] = *reinterpret_cast<const float4*>(xrA + q * 4);
            xb[i] = *reinterpret_cast<const float4*>(xrB + q * 4);
        }
        float s0a = 0.f, s1a = 0.f, s0b = 0.f, s1b = 0.f;
        #pragma unroll
        for (int i = 0; i < 4; i++) {
            const int q = i * NTH + t;
            const float4 a0 = sA0[q];
            const float4 a1 = sA1[q];
            s0a = fmaf(xa[i].x, a0.x, s0a); s0a = fmaf(xa[i].y, a0.y, s0a);
            s0a = fmaf(xa[i].z, a0.z, s0a); s0a = fmaf(xa[i].w, a0.w, s0a);
            s1a = fmaf(xa[i].x, a1.x, s1a); s1a = fmaf(xa[i].y, a1.y, s1a);
            s1a = fmaf(xa[i].z, a1.z, s1a); s1a = fmaf(xa[i].w, a1.w, s1a);
            s0b = fmaf(xb[i].x, a0.x, s0b); s0b = fmaf(xb[i].y, a0.y, s0b);
            s0b = fmaf(xb[i].z, a0.z, s0b); s0b = fmaf(xb[i].w, a0.w, s0b);
            s1b = fmaf(xb[i].x, a1.x, s1b); s1b = fmaf(xb[i].y, a1.y, s1b);
            s1b = fmaf(xb[i].z, a1.z, s1b); s1b = fmaf(xb[i].w, a1.w, s1b);
        }

        // ---- Warp reduce (4 values interleaved) ----
        #pragma unroll
        for (int o = 16; o > 0; o >>= 1) {
            s0a += __shfl_xor_sync(0xffffffffu, s0a, o);
            s1a += __shfl_xor_sync(0xffffffffu, s1a, o);
            s0b += __shfl_xor_sync(0xffffffffu, s0b, o);
            s1b += __shfl_xor_sync(0xffffffffu, s1b, o);
        }
        if (lane == 0) part[buf][wid] = make_float4(s0a, s1a, s0b, s1b);
        __syncthreads();   // the only barrier per 2 rows

        // ---- Redundant cross-warp final sum (broadcast LDS, no 2nd sync) ----
        float h0a = 0.f, h1a = 0.f, h0b = 0.f, h1b = 0.f;
        #pragma unroll
        for (int w = 0; w < NWARP; w++) {
            const float4 p = part[buf][w];
            h0a += p.x; h1a += p.y; h0b += p.z; h1b += p.w;
        }
        h0a *= as0; h1a *= as1;
        h0b *= as0; h1b *= as1;

        // ---- Phase 2: expansion, B weights read once for both rows ----
        float* outrA = out + (size_t)rowA * INNER_D;
        float* outrB = outrA + INNER_D;
        #pragma unroll
        for (int i = 0; i < 4; i++) {
            const int q = i * NTH + t;
            const float4 b0 = sB0[q];
            const float4 b1 = sB1[q];
            float4 oA, oB;
            oA.x = fmaf(h0a, b0.x, h1a * b1.x);
            oA.y = fmaf(h0a, b0.y, h1a * b1.y);
            oA.z = fmaf(h0a, b0.z, h1a * b1.z);
            oA.w = fmaf(h0a, b0.w, h1a * b1.w);
            oB.x = fmaf(h0b, b0.x, h1b * b1.x);
            oB.y = fmaf(h0b, b0.y, h1b * b1.y);
            oB.z = fmaf(h0b, b0.z, h1b * b1.z);
            oB.w = fmaf(h0b, b0.w, h1b * b1.w);
            __stcs(reinterpret_cast<float4*>(outrA) + q, oA);
            __stcs(reinterpret_cast<float4*>(outrB) + q, oB);
        }
    }
}

extern "C" void kernel_launch(void* const* d_in, const int* in_sizes, int n_in,
                              void* d_out, int out_size) {
    // Bind inputs by element count (robust to metadata ordering):
    //   67108864 -> x_in, 2 -> a_scale, 4096 -> b_scale,
    //   8192 (x2) -> a_q (first), b_q (second).
    const float* x      = nullptr;
    const int*   aq     = nullptr;
    const float* ascale = nullptr;
    const int*   bq     = nullptr;
    const float* bscale = nullptr;

    for (int i = 0; i < n_in; i++) {
        const int sz = in_sizes[i];
        if (sz == 2) {
            ascale = (const float*)d_in[i];
        } else if (sz == 4096) {
            bscale = (const float*)d_in[i];
        } else if (sz == 8192) {
            if (aq == nullptr) aq = (const int*)d_in[i];
            else               bq = (const int*)d_in[i];
        } else {
            x = (const float*)d_in[i];
        }
    }

    float* out = (float*)d_out;
    const int nrows = out_size / INNER_D;                 // 16384
    const int grid  = (nrows + R_PER_CTA - 1) / R_PER_CTA; // 1024
    qlora_r17_kernel<<<grid, NTH>>>(x, aq, ascale, bq, bscale, out, nrows);
}